// round 4
// baseline (speedup 1.0000x reference)
#include <cuda_runtime.h>

#define HW    160
#define NIMG  32
#define NBITS 128
#define SW    168
#define TH    16
#define TROWS 22
#define TILEN (TROWS * SW)     // 3696 floats
#define BITG  16
#define CGN   40               // column groups of 4
#define RGN   8                // row groups
#define RR    2                // rows per thread (320 thr = 40 cg x 8 rg)
#define NTHR  320

typedef unsigned long long u64;

struct __align__(16) BitP2 {
    float2 fx1, omfx1, fx2, omfx2;   // horizontal lerp weights (broadcast pairs)
    float2 B1, A1, B2n, A2n;         // 0.25*(1-fy1), 0.25*fy1, -0.25*(1-fy2), -0.25*fy2
    float2 c;                        // 0.125 - 0.25*th
    int    off1, off2, p0, p1;       // y1*SW + x1 per interp
};                                    // 96 bytes

#define SMEMB (BITG * (int)sizeof(BitP2) + 64 + 4 * TILEN * 4)

// ---- packed f32x2 helpers -------------------------------------------------
__device__ __forceinline__ u64 mul2(u64 a, u64 b) {
    u64 r; asm("mul.rn.f32x2 %0, %1, %2;" : "=l"(r) : "l"(a), "l"(b)); return r;
}
__device__ __forceinline__ u64 fma2(u64 a, u64 b, u64 c) {
    u64 r; asm("fma.rn.f32x2 %0, %1, %2, %3;" : "=l"(r) : "l"(a), "l"(b), "l"(c)); return r;
}
__device__ __forceinline__ u64 pk(float lo, float hi) {
    u64 r; asm("mov.b64 %0, {%1, %2};" : "=l"(r) : "f"(lo), "f"(hi)); return r;
}
__device__ __forceinline__ void upk(u64 v, float& lo, float& hi) {
    asm("mov.b64 {%0, %1}, %2;" : "=f"(lo), "=f"(hi) : "l"(v));
}

// ---------------------------------------------------------------------------
// Single fused kernel. Block = (16-row tile, 16-bit group, image), 320 thr.
// 40 col-groups (4 cols = one aligned LDS.128, 5th elem via shfl_down with
// scalar-LDS fallback at warp/strip boundaries) x 8 row-groups (2 rows each).
// 4 shifted smem tiles T[s][i] = pad[i+s] keep every LDS.128 aligned for any
// per-bit x offset. Packed f32x2 math; vertical lerp carried across rows.
// ---------------------------------------------------------------------------
__global__ __launch_bounds__(NTHR) void fern_main(const float* __restrict__ x,
                                                  const float* __restrict__ dx1,
                                                  const float* __restrict__ dx2,
                                                  const float* __restrict__ dy1,
                                                  const float* __restrict__ dy2,
                                                  const float* __restrict__ th,
                                                  float* __restrict__ out) {
    extern __shared__ __align__(16) char smraw[];
    BitP2* sp   = (BitP2*)smraw;
    float* wred = (float*)(smraw + BITG * sizeof(BitP2));
    float* T0   = (float*)(smraw + BITG * sizeof(BitP2) + 64);

    int tid = threadIdx.x;
    int h0  = blockIdx.x * TH;
    int bg  = blockIdx.y;
    int n   = blockIdx.z;

    // --- L = max|offset| (warp reductions; identical in every block) -------
    float m = 0.0f;
    if (tid < 128) {
        m = fmaxf(fmaxf(fabsf(dx1[tid]), fabsf(dx2[tid])),
                  fmaxf(fabsf(dy1[tid]), fabsf(dy2[tid])));
    }
#pragma unroll
    for (int o = 16; o; o >>= 1) m = fmaxf(m, __shfl_xor_sync(0xffffffffu, m, o));
    if (tid < 128 && (tid & 31) == 0) wred[tid >> 5] = m;

    // --- fill 4 shifted tiles from x (channel 1), zero-padded --------------
    const float* src = x + ((size_t)n * 3 + 1) * (HW * HW);
    for (int idx = tid; idx < TILEN; idx += NTHR) {
        int r = idx / SW, c = idx - r * SW;
        int h = h0 + r - 3, wc = c - 3;
        float v = 0.0f;
        if ((unsigned)h < HW && (unsigned)wc < HW) v = src[h * HW + wc];
        T0[idx] = v;
        if (idx >= 1) T0[TILEN + idx - 1] = v;
        if (idx >= 2) T0[2 * TILEN + idx - 2] = v;
        if (idx >= 3) T0[3 * TILEN + idx - 3] = v;
    }
    __syncthreads();

    // --- per-bit params for this block's 16 bits (reference-exact math) ----
    if (tid < BITG) {
        float L = fmaxf(fmaxf(wred[0], wred[1]), fmaxf(wred[2], wred[3]));
        int shift = 3 - (int)ceilf(L);
        int bit = bg * BITG + tid;
        BitP2 bp;
        {
            float dx = dx1[bit], dy = dy1[bit];
            float fdx = floorf(dx), fdy = floorf(dy);
            int x1 = (int)(L + fdx) + shift;    // trunc toward zero == astype(int32)
            int y1 = (int)(L + fdy) + shift;
            x1 = min(max(x1, 0), 5);            // dynamic_slice start clamp
            y1 = min(max(y1, 0), 5);
            bp.off1 = y1 * SW + x1;
            float fx = dx - fdx, fy = dy - fdy;
            bp.fx1   = make_float2(fx, fx);
            bp.omfx1 = make_float2(1.0f - fx, 1.0f - fx);
            bp.A1    = make_float2(0.25f * fy, 0.25f * fy);
            bp.B1    = make_float2(0.25f * (1.0f - fy), 0.25f * (1.0f - fy));
        }
        {
            float dx = dx2[bit], dy = dy2[bit];
            float fdx = floorf(dx), fdy = floorf(dy);
            int x1 = (int)(L + fdx) + shift;
            int y1 = (int)(L + fdy) + shift;
            x1 = min(max(x1, 0), 5);
            y1 = min(max(y1, 0), 5);
            bp.off2 = y1 * SW + x1;
            float fx = dx - fdx, fy = dy - fdy;
            bp.fx2   = make_float2(fx, fx);
            bp.omfx2 = make_float2(1.0f - fx, 1.0f - fx);
            bp.A2n   = make_float2(-0.25f * fy, -0.25f * fy);
            bp.B2n   = make_float2(-0.25f * (1.0f - fy), -0.25f * (1.0f - fy));
        }
        float cc = fmaf(-0.25f, th[bit], 0.125f);
        bp.c = make_float2(cc, cc);
        bp.p0 = bp.p1 = 0;
        sp[tid] = bp;
    }
    __syncthreads();

    // --- main loop ---------------------------------------------------------
    int cg  = tid % CGN;
    int rg  = tid / CGN;
    int ro0 = rg * RR;
    int col = cg * 4;
    bool fbp = (cg == CGN - 1) || ((tid & 31) == 31);

    float* outb = out + (((size_t)n * NBITS + bg * BITG) * HW + h0 + ro0) * HW + col;

    for (int b = 0; b < BITG; ++b) {
        const u64* pp = (const u64*)(sp + b);
        u64 fx1 = pp[0], om1 = pp[1], fx2 = pp[2], om2 = pp[3];
        u64 B1 = pp[4], A1 = pp[5], B2 = pp[6], A2 = pp[7], cc = pp[8];
        int off1 = ((const int*)(sp + b))[18];
        int off2 = ((const int*)(sp + b))[19];

        const float* p1 = T0 + (off1 & 3) * TILEN + ((off1 & ~3) + col + ro0 * SW);
        const float* f1 = T0 + off1 + col + 4 + ro0 * SW;
        const float* p2 = T0 + (off2 & 3) * TILEN + ((off2 & ~3) + col + ro0 * SW);
        const float* f2 = T0 + off2 + col + 4 + ro0 * SW;

        u64 t1a, t1b, t2a, t2b;
        {
            float4 F = *(const float4*)p1;
            float v4 = __shfl_down_sync(0xffffffffu, F.x, 1);
            if (fbp) v4 = f1[0];
            t1a = fma2(fx1, pk(F.y, F.z), mul2(om1, pk(F.x, F.y)));
            t1b = fma2(fx1, pk(F.w, v4),  mul2(om1, pk(F.z, F.w)));
        }
        {
            float4 F = *(const float4*)p2;
            float v4 = __shfl_down_sync(0xffffffffu, F.x, 1);
            if (fbp) v4 = f2[0];
            t2a = fma2(fx2, pk(F.y, F.z), mul2(om2, pk(F.x, F.y)));
            t2b = fma2(fx2, pk(F.w, v4),  mul2(om2, pk(F.z, F.w)));
        }

        float* op = outb + (size_t)b * (HW * HW);

#pragma unroll
        for (int hh = 1; hh <= RR; ++hh) {
            float4 F1 = *(const float4*)(p1 + hh * SW);
            float v41 = __shfl_down_sync(0xffffffffu, F1.x, 1);
            if (fbp) v41 = f1[hh * SW];
            u64 u1a = fma2(fx1, pk(F1.y, F1.z), mul2(om1, pk(F1.x, F1.y)));
            u64 u1b = fma2(fx1, pk(F1.w, v41),  mul2(om1, pk(F1.z, F1.w)));

            float4 F2 = *(const float4*)(p2 + hh * SW);
            float v42 = __shfl_down_sync(0xffffffffu, F2.x, 1);
            if (fbp) v42 = f2[hh * SW];
            u64 u2a = fma2(fx2, pk(F2.y, F2.z), mul2(om2, pk(F2.x, F2.y)));
            u64 u2b = fma2(fx2, pk(F2.w, v42),  mul2(om2, pk(F2.z, F2.w)));

            u64 ra = fma2(A2, u2a, fma2(B2, t2a, fma2(A1, u1a, fma2(B1, t1a, cc))));
            u64 rb = fma2(A2, u2b, fma2(B2, t2b, fma2(A1, u1b, fma2(B1, t1b, cc))));

            float r0, r1, r2, r3;
            upk(ra, r0, r1);
            upk(rb, r2, r3);
            float4 o;
            o.x = __saturatef(r0);
            o.y = __saturatef(r1);
            o.z = __saturatef(r2);
            o.w = __saturatef(r3);
            *(float4*)(op + (size_t)(hh - 1) * HW) = o;

            t1a = u1a; t1b = u1b; t2a = u2a; t2b = u2b;
        }
    }
}

// ---------------------------------------------------------------------------
extern "C" void kernel_launch(void* const* d_in, const int* in_sizes, int n_in,
                              void* d_out, int out_size) {
    const float* x   = (const float*)d_in[0];
    const float* dx1 = (const float*)d_in[1];
    const float* dx2 = (const float*)d_in[2];
    const float* dy1 = (const float*)d_in[3];
    const float* dy2 = (const float*)d_in[4];
    const float* th  = (const float*)d_in[5];

    static int attr_done = 0;
    if (!attr_done) {
        cudaFuncSetAttribute(fern_main, cudaFuncAttributeMaxDynamicSharedMemorySize, SMEMB);
        attr_done = 1;
    }

    dim3 grid(HW / TH, NBITS / BITG, NIMG);
    fern_main<<<grid, NTHR, SMEMB>>>(x, dx1, dx2, dy1, dy2, th, (float*)d_out);
}

// round 5
// speedup vs baseline: 1.2991x; 1.2991x over previous
#include <cuda_runtime.h>
#include <cuda_fp16.h>

#define HW    160
#define NIMG  32
#define NBITS 128
#define SW    168
#define TH    16
#define TROWS 22
#define TILEN (TROWS * SW)     // 3696
#define BITG  32
#define NTHR  160

struct __align__(16) BitH {
    __half2 fx1, fx2, B1, A1, B2n, A2n, c;   // 28 B
    int off1, off2;                           // y1*SW + x1 per interp
    int pad;                                  // -> 40 B
};

// ---------------------------------------------------------------------------
// Single fused kernel. Block = (16-row tile, 32-bit group, image), 160 thr =
// 80 column-pairs x 2 row-groups (8 rows each).
// Pair-tile Q[i] = (p[i], p[i+1]) as half2: lo pair = Q[x] and hi pair =
// Q[x+1] are each ONE aligned LDS.32 for any offset — no parity tiles, no
// shfl. All interp math in half2 (HFMA2); convert to f32 only at the store.
// Vertical lerp carried across the 8 rows.
// ---------------------------------------------------------------------------
__global__ __launch_bounds__(NTHR) void fern_main(const float* __restrict__ x,
                                                  const float* __restrict__ dx1,
                                                  const float* __restrict__ dx2,
                                                  const float* __restrict__ dy1,
                                                  const float* __restrict__ dy2,
                                                  const float* __restrict__ th,
                                                  float* __restrict__ out) {
    __shared__ __align__(16) __half Qh[2 * TILEN];
    __shared__ BitH  sp[BITG];
    __shared__ float wred[4];

    int tid = threadIdx.x;
    int h0  = blockIdx.x * TH;
    int bg  = blockIdx.y;
    int n   = blockIdx.z;

    // --- L = max|offset| (warp reductions; identical in every block) -------
    float m = 0.0f;
    if (tid < 128) {
        m = fmaxf(fmaxf(fabsf(dx1[tid]), fabsf(dx2[tid])),
                  fmaxf(fabsf(dy1[tid]), fabsf(dy2[tid])));
    }
#pragma unroll
    for (int o = 16; o; o >>= 1) m = fmaxf(m, __shfl_xor_sync(0xffffffffu, m, o));
    if (tid < 128 && (tid & 31) == 0) wred[tid >> 5] = m;

    // --- fill pair-tile from x (channel 1), zero-padded --------------------
    const float* src = x + ((size_t)n * 3 + 1) * (HW * HW);
    for (int idx = tid; idx < TILEN; idx += NTHR) {
        int r = idx / SW, c = idx - r * SW;
        int h = h0 + r - 3, wc = c - 3;
        float v = 0.0f;
        if ((unsigned)h < HW && (unsigned)wc < HW) v = src[h * HW + wc];
        __half hv = __float2half(v);
        Qh[2 * idx] = hv;                    // pair idx, first element
        if (idx) Qh[2 * idx - 1] = hv;       // pair idx-1, second element
    }
    __syncthreads();

    // --- per-bit params for this block's 32 bits (reference-exact idx math)
    if (tid < BITG) {
        float L = fmaxf(fmaxf(wred[0], wred[1]), fmaxf(wred[2], wred[3]));
        int shift = 3 - (int)ceilf(L);
        int bit = bg * BITG + tid;
        BitH bp;
        {
            float dx = dx1[bit], dy = dy1[bit];
            float fdx = floorf(dx), fdy = floorf(dy);
            int x1 = (int)(L + fdx) + shift;    // trunc toward zero == astype(int32)
            int y1 = (int)(L + fdy) + shift;
            x1 = min(max(x1, 0), 5);            // dynamic_slice start clamp
            y1 = min(max(y1, 0), 5);
            bp.off1 = y1 * SW + x1;
            float fx = dx - fdx, fy = dy - fdy;
            bp.fx1 = __float2half2_rn(fx);
            bp.A1  = __float2half2_rn(0.25f * fy);
            bp.B1  = __float2half2_rn(0.25f * (1.0f - fy));
        }
        {
            float dx = dx2[bit], dy = dy2[bit];
            float fdx = floorf(dx), fdy = floorf(dy);
            int x1 = (int)(L + fdx) + shift;
            int y1 = (int)(L + fdy) + shift;
            x1 = min(max(x1, 0), 5);
            y1 = min(max(y1, 0), 5);
            bp.off2 = y1 * SW + x1;
            float fx = dx - fdx, fy = dy - fdy;
            bp.fx2 = __float2half2_rn(fx);
            bp.A2n = __float2half2_rn(-0.25f * fy);
            bp.B2n = __float2half2_rn(-0.25f * (1.0f - fy));
        }
        bp.c = __float2half2_rn(fmaf(-0.25f, th[bit], 0.125f));
        bp.pad = 0;
        sp[tid] = bp;
    }
    __syncthreads();

    // --- main loop ---------------------------------------------------------
    int p   = tid % 80;          // column pair
    int wp  = 2 * p;
    int ro0 = (tid / 80) * 8;    // first output row of this thread

    const __half2 ZERO = __float2half2_rn(0.0f);
    const __half2 ONE  = __float2half2_rn(1.0f);

    float* outb = out + (((size_t)n * NBITS + bg * BITG) * HW + h0 + ro0) * HW + wp;

    for (int b = 0; b < BITG; ++b) {
        BitH bp = sp[b];

        const __half2* q1 = (const __half2*)Qh + (bp.off1 + wp + ro0 * SW);
        const __half2* q2 = (const __half2*)Qh + (bp.off2 + wp + ro0 * SW);

        // carry init: horizontal lerp at this thread's first window row
        __half2 lo = q1[0], hi = q1[1];
        __half2 t1 = __hfma2(bp.fx1, __hsub2(hi, lo), lo);
        lo = q2[0]; hi = q2[1];
        __half2 t2 = __hfma2(bp.fx2, __hsub2(hi, lo), lo);

        float* op = outb + (size_t)b * (HW * HW);

#pragma unroll
        for (int hh = 1; hh <= 8; ++hh) {
            __half2 a0 = q1[hh * SW], a1 = q1[hh * SW + 1];
            __half2 u1 = __hfma2(bp.fx1, __hsub2(a1, a0), a0);
            __half2 b0 = q2[hh * SW], b1 = q2[hh * SW + 1];
            __half2 u2 = __hfma2(bp.fx2, __hsub2(b1, b0), b0);

            __half2 v = __hfma2(bp.B1, t1, bp.c);
            v = __hfma2(bp.A1,  u1, v);
            v = __hfma2(bp.B2n, t2, v);
            v = __hfma2(bp.A2n, u2, v);
            v = __hmax2(v, ZERO);
            v = __hmin2(v, ONE);

            float2 f = __half22float2(v);
            *(float2*)(op + (size_t)(hh - 1) * HW) = f;

            t1 = u1;
            t2 = u2;
        }
    }
}

// ---------------------------------------------------------------------------
extern "C" void kernel_launch(void* const* d_in, const int* in_sizes, int n_in,
                              void* d_out, int out_size) {
    const float* x   = (const float*)d_in[0];
    const float* dx1 = (const float*)d_in[1];
    const float* dx2 = (const float*)d_in[2];
    const float* dy1 = (const float*)d_in[3];
    const float* dy2 = (const float*)d_in[4];
    const float* th  = (const float*)d_in[5];

    dim3 grid(HW / TH, NBITS / BITG, NIMG);
    fern_main<<<grid, NTHR>>>(x, dx1, dx2, dy1, dy2, th, (float*)d_out);
}

// round 6
// speedup vs baseline: 1.4501x; 1.1162x over previous
#include <cuda_runtime.h>
#include <cuda_fp16.h>

#define HW    160
#define NIMG  32
#define NBITS 128
#define SW    168
#define TH    16
#define TROWS 22
#define TILEN (TROWS * SW)     // 3696 pair entries
#define BITG  32
#define NTHR  160

typedef unsigned long long u64;

struct __align__(16) BitH {
    __half2 fx1, fx2, B1, A1, B2n, A2n, c;   // 28 B
    int off1, off2;                           // y1*SW + x1 per interp
    int pad;                                  // -> 40 B
};

// ---------------------------------------------------------------------------
// Single fused kernel. Block = (16-row tile, 32-bit group, image), 160 thr =
// 80 column-pairs x 2 row-groups (8 rows each).
// Tiles (half, 8-B aligned u64 view):
//   QA: (p[s],p[s+1]) pairs;  QA64[j] = (p[2j],p[2j+1],p[2j+1],p[2j+2])
//   QB: shifted one pair;      QB64[j] = (p[2j+1],p[2j+2],p[2j+2],p[2j+3])
// For pair index s (any parity), (lo,hi) = one aligned LDS.64 from
// (s&1 ? QB : QA) at u64 index s>>1; lanes are consecutive u64 -> fully-used
// 256B/warp. Parity of s is per-bit constant (off&1) -> hoisted select.
// All interp math half2 (HFMA2); vertical lerp carried across 8 rows.
// ---------------------------------------------------------------------------
__global__ __launch_bounds__(NTHR) void fern_main(const float* __restrict__ x,
                                                  const float* __restrict__ dx1,
                                                  const float* __restrict__ dx2,
                                                  const float* __restrict__ dy1,
                                                  const float* __restrict__ dy2,
                                                  const float* __restrict__ th,
                                                  float* __restrict__ out) {
    __shared__ __align__(16) __half QA[2 * TILEN];
    __shared__ __align__(16) __half QB[2 * TILEN];
    __shared__ BitH  sp[BITG];
    __shared__ float wred[4];

    int tid = threadIdx.x;
    int h0  = blockIdx.x * TH;
    int bg  = blockIdx.y;
    int n   = blockIdx.z;

    // --- L = max|offset| (warp reductions; identical in every block) -------
    float m = 0.0f;
    if (tid < 128) {
        m = fmaxf(fmaxf(fabsf(dx1[tid]), fabsf(dx2[tid])),
                  fmaxf(fabsf(dy1[tid]), fabsf(dy2[tid])));
    }
#pragma unroll
    for (int o = 16; o; o >>= 1) m = fmaxf(m, __shfl_xor_sync(0xffffffffu, m, o));
    if (tid < 128 && (tid & 31) == 0) wred[tid >> 5] = m;

    // --- fill both tiles from x (channel 1), zero-padded -------------------
    // QA_half[2i] = QA_half[2i-1] = p[i];  QB_half[2i-2] = QB_half[2i-3] = p[i]
    const float* src = x + ((size_t)n * 3 + 1) * (HW * HW);
    for (int idx = tid; idx < TILEN; idx += NTHR) {
        int r = idx / SW, c = idx - r * SW;
        int h = h0 + r - 3, wc = c - 3;
        float v = 0.0f;
        if ((unsigned)h < HW && (unsigned)wc < HW) v = src[h * HW + wc];
        __half hv = __float2half(v);
        QA[2 * idx] = hv;
        if (idx >= 1) { QA[2 * idx - 1] = hv; QB[2 * idx - 2] = hv; }
        if (idx >= 2) { QB[2 * idx - 3] = hv; }
    }
    __syncthreads();

    // --- per-bit params (reference-exact index math) -----------------------
    if (tid < BITG) {
        float L = fmaxf(fmaxf(wred[0], wred[1]), fmaxf(wred[2], wred[3]));
        int shift = 3 - (int)ceilf(L);
        int bit = bg * BITG + tid;
        BitH bp;
        {
            float dx = dx1[bit], dy = dy1[bit];
            float fdx = floorf(dx), fdy = floorf(dy);
            int x1 = (int)(L + fdx) + shift;    // trunc toward zero == astype(int32)
            int y1 = (int)(L + fdy) + shift;
            x1 = min(max(x1, 0), 5);            // dynamic_slice start clamp
            y1 = min(max(y1, 0), 5);
            bp.off1 = y1 * SW + x1;
            float fx = dx - fdx, fy = dy - fdy;
            bp.fx1 = __float2half2_rn(fx);
            bp.A1  = __float2half2_rn(0.25f * fy);
            bp.B1  = __float2half2_rn(0.25f * (1.0f - fy));
        }
        {
            float dx = dx2[bit], dy = dy2[bit];
            float fdx = floorf(dx), fdy = floorf(dy);
            int x1 = (int)(L + fdx) + shift;
            int y1 = (int)(L + fdy) + shift;
            x1 = min(max(x1, 0), 5);
            y1 = min(max(y1, 0), 5);
            bp.off2 = y1 * SW + x1;
            float fx = dx - fdx, fy = dy - fdy;
            bp.fx2 = __float2half2_rn(fx);
            bp.A2n = __float2half2_rn(-0.25f * fy);
            bp.B2n = __float2half2_rn(-0.25f * (1.0f - fy));
        }
        bp.c = __float2half2_rn(fmaf(-0.25f, th[bit], 0.125f));
        bp.pad = 0;
        sp[tid] = bp;
    }
    __syncthreads();

    // --- main loop ---------------------------------------------------------
    int p   = tid % 80;          // column pair
    int wp  = 2 * p;
    int ro0 = (tid / 80) * 8;    // first output row of this thread

    const __half2 ZERO = __float2half2_rn(0.0f);
    const __half2 ONE  = __float2half2_rn(1.0f);

    float* outb = out + (((size_t)n * NBITS + bg * BITG) * HW + h0 + ro0) * HW + wp;

    for (int b = 0; b < BITG; ++b) {
        BitH bp = sp[b];

        const uint2* q1 = (const uint2*)((bp.off1 & 1) ? QB : QA)
                          + ((bp.off1 + wp + ro0 * SW) >> 1);
        const uint2* q2 = (const uint2*)((bp.off2 & 1) ? QB : QA)
                          + ((bp.off2 + wp + ro0 * SW) >> 1);

        // carry init: horizontal lerp at this thread's first window row
        uint2 u = q1[0];
        __half2 lo = *(__half2*)&u.x, hi = *(__half2*)&u.y;
        __half2 t1 = __hfma2(bp.fx1, __hsub2(hi, lo), lo);
        u = q2[0];
        lo = *(__half2*)&u.x; hi = *(__half2*)&u.y;
        __half2 t2 = __hfma2(bp.fx2, __hsub2(hi, lo), lo);

        float* op = outb + (size_t)b * (HW * HW);

#pragma unroll
        for (int hh = 1; hh <= 8; ++hh) {
            uint2 ua = q1[hh * (SW / 2)];
            __half2 a0 = *(__half2*)&ua.x, a1 = *(__half2*)&ua.y;
            __half2 u1 = __hfma2(bp.fx1, __hsub2(a1, a0), a0);
            uint2 ub = q2[hh * (SW / 2)];
            __half2 b0 = *(__half2*)&ub.x, b1 = *(__half2*)&ub.y;
            __half2 u2 = __hfma2(bp.fx2, __hsub2(b1, b0), b0);

            __half2 v = __hfma2(bp.B1, t1, bp.c);
            v = __hfma2(bp.A1,  u1, v);
            v = __hfma2(bp.B2n, t2, v);
            v = __hfma2(bp.A2n, u2, v);
            v = __hmax2(v, ZERO);
            v = __hmin2(v, ONE);

            float2 f = __half22float2(v);
            *(float2*)(op + (size_t)(hh - 1) * HW) = f;

            t1 = u1;
            t2 = u2;
        }
    }
}

// ---------------------------------------------------------------------------
extern "C" void kernel_launch(void* const* d_in, const int* in_sizes, int n_in,
                              void* d_out, int out_size) {
    const float* x   = (const float*)d_in[0];
    const float* dx1 = (const float*)d_in[1];
    const float* dx2 = (const float*)d_in[2];
    const float* dy1 = (const float*)d_in[3];
    const float* dy2 = (const float*)d_in[4];
    const float* th  = (const float*)d_in[5];

    dim3 grid(HW / TH, NBITS / BITG, NIMG);
    fern_main<<<grid, NTHR>>>(x, dx1, dx2, dy1, dy2, th, (float*)d_out);
}